// round 3
// baseline (speedup 1.0000x reference)
#include <cuda_runtime.h>
#include <cstdint>

// Locally-connected 2D:
//   out[b,o,y,x] = sum_k patches[b,y,x,k] * W[y,x,o,k] + bias[y,x,o]
// x: [128,3,64,64] f32, W: [60,60,32,75] f32 (k = c*25+kh*5+kw),
// bias: [60,60,32] f32, out: [128,32,60,60] f32

#define RYX   60
#define OC    32
#define KTOT  75
#define TX    4      // output positions per CTA
#define BH    64     // batches per CTA (half)
#define SXS   68     // sX row stride (64 + 4 pad)
#define SWS   132    // sW per-k stride (4*32 + 4 pad)

typedef unsigned long long ull;

__device__ float g_xT[3 * 64 * 64 * 128];   // x transposed: [c][h][w][b]

// ---------------------------------------------------------------- transpose
__global__ __launch_bounds__(256)
void transpose_x_kernel(const float* __restrict__ x)
{
    __shared__ float tile[32][33];
    const int wt    = blockIdx.x & 1;
    const int btile = blockIdx.x >> 1;
    const int h     = blockIdx.y;
    const int c     = blockIdx.z;
    const int tx = threadIdx.x;
    const int ty = threadIdx.y;

    #pragma unroll
    for (int j = 0; j < 4; j++) {
        int b = btile * 32 + ty + j * 8;
        tile[ty + j * 8][tx] =
            x[(((size_t)b * 3 + c) * 64 + h) * 64 + wt * 32 + tx];
    }
    __syncthreads();
    #pragma unroll
    for (int j = 0; j < 4; j++) {
        int w = wt * 32 + ty + j * 8;
        g_xT[(((size_t)c * 64 + h) * 64 + w) * 128 + btile * 32 + tx] =
            tile[tx][ty + j * 8];
    }
}

// ---------------------------------------------------------------- main
__global__ __launch_bounds__(256, 3)
void lc2d_kernel(const float* __restrict__ W,
                 const float* __restrict__ bias,
                 float* __restrict__ out)
{
    extern __shared__ float smem[];
    float* sW = smem;                    // KTOT * SWS = 9900 floats  [k][pl*32 + swz(o)]
    float* sX = sW + KTOT * SWS;         // 120 * SXS  = 8160 floats  [(c*5+r)*8+col][b]
    float* sB = sX + 120 * SXS;          // 128 floats                [pl*32 + o]

    const int xt    = blockIdx.x;          // 15
    const int py    = blockIdx.y;          // 60
    const int bhalf = blockIdx.z;          // 2
    const int px0   = xt * TX;
    const int pos0  = py * RYX + px0;
    const int t     = threadIdx.x;

    // ---- W fill: contiguous 9600-float coalesced read -> k-major padded smem ----
    const float* Wg = W + (size_t)pos0 * (OC * KTOT);
    #pragma unroll 5
    for (int i = t; i < TX * OC * KTOT; i += 256) {
        int row = i / KTOT;                 // pl*32 + o
        int k   = i - row * KTOT;
        int pl_ = row >> 5;
        int o   = row & 31;
        sW[k * SWS + pl_ * 32 + ((o + 4 * (pl_ & 1)) & 31)] = Wg[i];
    }
    if (t < TX * OC) sB[t] = bias[pos0 * OC + t];

    // ---- x fill from xT: float4 coalesced both sides ----
    #pragma unroll 4
    for (int i = t; i < 120 * 16; i += 256) {
        int bq   = i & 15;
        int comb = i >> 4;                  // (c*5+r)*8 + col
        int c    = comb / 40;
        int rem  = comb - c * 40;
        int r    = rem >> 3;
        int col  = rem & 7;
        float4 v = *reinterpret_cast<const float4*>(
            &g_xT[(((size_t)c * 64 + py + r) * 64 + px0 + col) * 128
                  + bhalf * BH + bq * 4]);
        *reinterpret_cast<float4*>(&sX[comb * SXS + bq * 4]) = v;
    }
    __syncthreads();

    // ---- compute: thread = (pl, ot, bt); tile 8o x 4b, packed f32x2 ----
    const int pl = t & 3;
    const int ot = (t >> 2) & 3;
    const int bt = t >> 4;              // 0..15
    const int o0 = ot * 8;
    const int b0 = bt * 4;
    const int plsw = (pl & 1) * 4;

    const float* wbase = sW + pl * 32;
    const float* xbase = sX + b0;

    ull acc[16];
    #pragma unroll
    for (int i = 0; i < 16; i++) acc[i] = 0ull;

    #pragma unroll
    for (int cr = 0; cr < 15; cr++) {           // c*5 + r
        #pragma unroll
        for (int cc = 0; cc < 5; cc++) {
            const int k = cr * 5 + cc;
            ulonglong2 q = *reinterpret_cast<const ulonglong2*>(
                &xbase[(cr * 8 + pl + cc) * SXS]);
            float4 wa = *reinterpret_cast<const float4*>(
                &wbase[k * SWS + ((o0 + plsw) & 31)]);
            float4 wb = *reinterpret_cast<const float4*>(
                &wbase[k * SWS + ((o0 + 4 + plsw) & 31)]);
            const float wf[8] = {wa.x, wa.y, wa.z, wa.w, wb.x, wb.y, wb.z, wb.w};
            #pragma unroll
            for (int oi = 0; oi < 8; oi++) {
                unsigned wu = __float_as_uint(wf[oi]);
                ull wd;
                asm("mov.b64 %0, {%1, %1};" : "=l"(wd) : "r"(wu));
                asm("fma.rn.f32x2 %0, %1, %2, %0;" : "+l"(acc[oi*2+0]) : "l"(wd), "l"(q.x));
                asm("fma.rn.f32x2 %0, %1, %2, %0;" : "+l"(acc[oi*2+1]) : "l"(wd), "l"(q.y));
            }
        }
    }

    // ---- store: pl-adjacent lanes merge into 16B segments ----
    const int posidx = pos0 + pl;
    const int bg0    = bhalf * BH + b0;
    #pragma unroll
    for (int oi = 0; oi < 8; oi++) {
        const float bv = sB[pl * OC + o0 + oi];
        #pragma unroll
        for (int j = 0; j < 2; j++) {
            unsigned lo, hi;
            asm("mov.b64 {%0, %1}, %2;" : "=r"(lo), "=r"(hi) : "l"(acc[oi*2+j]));
            const size_t base =
                ((size_t)(bg0 + 2*j) * OC + o0 + oi) * (RYX * RYX) + posidx;
            out[base]                            = __uint_as_float(lo) + bv;
            out[base + (size_t)OC * RYX * RYX]   = __uint_as_float(hi) + bv;
        }
    }
}

// ---------------------------------------------------------------- launch
extern "C" void kernel_launch(void* const* d_in, const int* in_sizes, int n_in,
                              void* d_out, int out_size)
{
    const float* x    = (const float*)d_in[0];
    const float* W    = (const float*)d_in[1];
    const float* bias = (const float*)d_in[2];
    float* out        = (float*)d_out;

    static const int SMEM_BYTES = (KTOT * SWS + 120 * SXS + 128) * 4; // 72752
    cudaFuncSetAttribute(lc2d_kernel,
                         cudaFuncAttributeMaxDynamicSharedMemorySize, SMEM_BYTES);

    transpose_x_kernel<<<dim3(8, 64, 3), dim3(32, 8)>>>(x);
    lc2d_kernel<<<dim3(15, RYX, 2), 256, SMEM_BYTES>>>(W, bias, out);
}

// round 5
// speedup vs baseline: 1.3488x; 1.3488x over previous
#include <cuda_runtime.h>
#include <cuda_bf16.h>
#include <cstdint>

// Locally-connected 2D via mma.sync m16n8k16 bf16, 3-pass hi/lo split.
//   out[b,o,y,x] = sum_k patches[b,y,x,k] * W[y,x,o,k] + bias[y,x,o]
// x: [128,3,64,64] f32, W: [60,60,32,75] f32 (k = c*25+kh*5+kw),
// bias: [60,60,32] f32, out: [128,32,60,60] f32.
// Per position: D[128x32] = A[128x75] @ B[75x32] (B stored [o][k], mma row.col).

#define RYX  60
#define TX   4        // positions per CTA
#define XC   8        // x cols staged (TX + 4)
#define SXB  132      // sXp row stride (u32); bank = 4*rc + b
#define WROW 44       // sW per-o row stride (u32 pairs); conflict-free lane map

// ---- smem layout (bytes) ----
#define XP_BYTES   (120 * SXB * 4)              // 63360
#define WHI_OFF    XP_BYTES
#define WLO_OFF    (WHI_OFF + TX * 32 * WROW * 4)   // +22528
#define BIAS_OFF   (WLO_OFF + TX * 32 * WROW * 4)   // +22528
#define SMEM_TOTAL (BIAS_OFF + 512)             // 108928

__device__ unsigned g_xp[3 * 64 * 64 * 128];    // packed (bf16hi<<16)|bf16lo, b fastest

// ---------------------------------------------------------------- prep: pack x
__global__ __launch_bounds__(256)
void prep_x_kernel(const float* __restrict__ x)
{
    __shared__ unsigned tile[32][33];
    const int wt    = blockIdx.x & 1;
    const int btile = blockIdx.x >> 1;
    const int h     = blockIdx.y;
    const int c     = blockIdx.z;
    const int tx = threadIdx.x, ty = threadIdx.y;

    #pragma unroll
    for (int j = 0; j < 4; j++) {
        int b = btile * 32 + ty + j * 8;
        float v = x[(((size_t)b * 3 + c) * 64 + h) * 64 + wt * 32 + tx];
        __nv_bfloat16 hi = __float2bfloat16_rn(v);
        __nv_bfloat16 lo = __float2bfloat16_rn(v - __bfloat162float(hi));
        tile[ty + j * 8][tx] = ((unsigned)__bfloat16_as_ushort(hi) << 16)
                             |  (unsigned)__bfloat16_as_ushort(lo);
    }
    __syncthreads();
    #pragma unroll
    for (int j = 0; j < 4; j++) {
        int w = wt * 32 + ty + j * 8;
        g_xp[(((size_t)c * 64 + h) * 64 + w) * 128 + btile * 32 + tx] = tile[tx][ty + j * 8];
    }
}

// ---------------------------------------------------------------- helpers
__device__ __forceinline__ int rcof(int k) {       // smem row for flat k (pos 0)
    int c = k / 25, r = (k % 25) / 5, w = k % 5;
    return (c * 5 + r) * 8 + w;
}
__device__ __forceinline__ void mma_bf16(float* d, const unsigned* a, unsigned b0, unsigned b1) {
    asm volatile(
        "mma.sync.aligned.m16n8k16.row.col.f32.bf16.bf16.f32 "
        "{%0,%1,%2,%3}, {%4,%5,%6,%7}, {%8,%9}, {%0,%1,%2,%3};"
        : "+f"(d[0]), "+f"(d[1]), "+f"(d[2]), "+f"(d[3])
        : "r"(a[0]), "r"(a[1]), "r"(a[2]), "r"(a[3]), "r"(b0), "r"(b1));
}

// ---------------------------------------------------------------- main
__global__ __launch_bounds__(256, 2)
void lc2d_hmma_kernel(const float* __restrict__ W,
                      const float* __restrict__ bias,
                      float* __restrict__ out)
{
    extern __shared__ char smem[];
    unsigned* sXp   = (unsigned*)smem;              // [120 rc][SXB] packed u32
    unsigned* sWhi  = (unsigned*)(smem + WHI_OFF);  // [TX*32 o-rows][WROW] k-pairs
    unsigned* sWlo  = (unsigned*)(smem + WLO_OFF);
    float*    sBias = (float*)(smem + BIAS_OFF);    // [TX][32]

    const int xt   = blockIdx.x;          // 15
    const int py   = blockIdx.y;          // 60
    const int px0  = xt * TX;
    const int pos0 = py * RYX + px0;
    const int tid  = threadIdx.x;

    // ---- stage x tile: uint4 coalesced ----
    for (int i = tid; i < 120 * 32; i += 256) {
        int q    = i & 31;
        int rc   = i >> 5;                 // (c*5+kh)*8 + col
        int crow = rc >> 3, col = rc & 7;
        int c = crow / 5, kh = crow % 5;
        uint4 v = *reinterpret_cast<const uint4*>(
            &g_xp[(((size_t)c * 64 + py + kh) * 64 + px0 + col) * 128 + q * 4]);
        *reinterpret_cast<uint4*>(&sXp[rc * SXB + q * 4]) = v;
    }

    // ---- stage W: f32 -> (trunc-hi, rn-lo) bf16, interleaved pair layout ----
    // pair index kp=k>>1; within group of 8: f = (j&3)*2 + (j>>2) so that
    // frag pairs (tg+8s, tg+4+8s) land adjacent -> one LDS.64.
    {
        const float* Wg = W + (size_t)pos0 * (32 * 75);
        unsigned short* whi = (unsigned short*)sWhi;
        unsigned short* wlo = (unsigned short*)sWlo;
        for (int i = tid; i < TX * 32 * 80; i += 256) {
            int po = i / 80;               // p*32 + o
            int k  = i - po * 80;
            float v = (k < 75) ? Wg[po * 75 + k] : 0.0f;
            unsigned wb = __float_as_uint(v);
            unsigned short h_us = (unsigned short)(wb >> 16);
            float lo = v - __uint_as_float(wb & 0xFFFF0000u);
            unsigned short l_us = __bfloat16_as_ushort(__float2bfloat16_rn(lo));
            int kp = k >> 1, s = kp >> 3, j = kp & 7;
            int f  = ((j & 3) << 1) | (j >> 2);
            int idx = ((po * WROW + s * 8 + f) << 1) | (k & 1);
            whi[idx] = h_us;
            wlo[idx] = l_us;
        }
    }
    if (tid < TX * 32) sBias[tid] = bias[pos0 * 32 + tid];
    __syncthreads();

    // ---- compute: warp = (position p, m-half mh); 4 m-tiles x 4 n-tiles ----
    const int wid  = tid >> 5;
    const int lane = tid & 31;
    const int gid  = lane >> 2;
    const int tg   = lane & 3;
    const int p    = wid >> 1;
    const int mh   = wid & 1;

    float acc[4][4][4];
    #pragma unroll
    for (int mt = 0; mt < 4; mt++)
        #pragma unroll
        for (int nt = 0; nt < 4; nt++)
            #pragma unroll
            for (int r = 0; r < 4; r++) acc[mt][nt][r] = 0.0f;

    const unsigned* wh = sWhi + (p * 32 + gid) * WROW + 2 * tg;
    const unsigned* wl = sWlo + (p * 32 + gid) * WROW + 2 * tg;

    #pragma unroll
    for (int s = 0; s < 5; s++) {
        // B fragments: 4 n-tiles, hi+lo, one uint2 each
        unsigned bh[4][2], bl[4][2];
        #pragma unroll
        for (int nt = 0; nt < 4; nt++) {
            uint2 h = *reinterpret_cast<const uint2*>(wh + nt * 8 * WROW + s * 8);
            uint2 l = *reinterpret_cast<const uint2*>(wl + nt * 8 * WROW + s * 8);
            bh[nt][0] = h.x; bh[nt][1] = h.y;
            bl[nt][0] = l.x; bl[nt][1] = l.y;
        }

        // A row offsets for k0, k0+1, k0+8, k0+9 (u32 index, incl. position)
        const int k0 = 16 * s + 2 * tg;
        int off0, off1, off2, off3;
        bool v2 = true, v3 = true;
        if (s < 4) {
            off0 = (rcof(k0)     + p) * SXB;
            off1 = (rcof(k0 + 1) + p) * SXB;
            off2 = (rcof(k0 + 8) + p) * SXB;
            off3 = (rcof(k0 + 9) + p) * SXB;
        } else {
            off0 = (rcof(k0)     + p) * SXB;          // k0   = 64+2tg <= 70: valid
            off1 = (rcof(k0 + 1) + p) * SXB;          // <= 71: valid
            v2 = (k0 + 8) < 75;  off2 = v2 ? (rcof(k0 + 8) + p) * SXB : 0;
            v3 = (k0 + 9) < 75;  off3 = v3 ? (rcof(k0 + 9) + p) * SXB : 0;
        }

        #pragma unroll
        for (int mt = 0; mt < 4; mt++) {
            const int b = mh * 64 + mt * 16 + gid;
            unsigned x0 = sXp[off0 + b];
            unsigned x1 = sXp[off1 + b];
            unsigned x2 = sXp[off0 + b + 8];
            unsigned x3 = sXp[off1 + b + 8];
            unsigned x4 = v2 ? sXp[off2 + b]     : 0u;
            unsigned x5 = v3 ? sXp[off3 + b]     : 0u;
            unsigned x6 = v2 ? sXp[off2 + b + 8] : 0u;
            unsigned x7 = v3 ? sXp[off3 + b + 8] : 0u;

            unsigned ah[4], al[4];
            ah[0] = __byte_perm(x0, x1, 0x7632);  al[0] = __byte_perm(x0, x1, 0x5410);
            ah[1] = __byte_perm(x2, x3, 0x7632);  al[1] = __byte_perm(x2, x3, 0x5410);
            ah[2] = __byte_perm(x4, x5, 0x7632);  al[2] = __byte_perm(x4, x5, 0x5410);
            ah[3] = __byte_perm(x6, x7, 0x7632);  al[3] = __byte_perm(x6, x7, 0x5410);

            #pragma unroll
            for (int nt = 0; nt < 4; nt++) {
                mma_bf16(acc[mt][nt], ah, bh[nt][0], bh[nt][1]);   // hi*hi
                mma_bf16(acc[mt][nt], ah, bl[nt][0], bl[nt][1]);   // hi*lo
                mma_bf16(acc[mt][nt], al, bh[nt][0], bh[nt][1]);   // lo*hi
            }
        }
    }

    // ---- repack: sRep[px][b][o-pair] float2 (overlay, all inputs dead) ----
    __syncthreads();
    float2* sRep = (float2*)smem;        // [(p*128 + b)*17 + nt*4 + tg]
    #pragma unroll
    for (int mt = 0; mt < 4; mt++) {
        #pragma unroll
        for (int rh = 0; rh < 2; rh++) {
            const int b = mh * 64 + mt * 16 + gid + rh * 8;
            #pragma unroll
            for (int nt = 0; nt < 4; nt++) {
                sRep[(p * 128 + b) * 17 + nt * 4 + tg] =
                    make_float2(acc[mt][nt][rh * 2], acc[mt][nt][rh * 2 + 1]);
            }
        }
    }
    __syncthreads();

    // ---- store: float4 over px (16B contiguous) ----
    const float* rf = (const float*)smem;
    for (int j = tid; j < 128 * 32; j += 256) {
        int b = j >> 5, o = j & 31;
        float4 v;
        v.x = rf[((0 * 128 + b) * 34) + o] + sBias[0 * 32 + o];
        v.y = rf[((1 * 128 + b) * 34) + o] + sBias[1 * 32 + o];
        v.z = rf[((2 * 128 + b) * 34) + o] + sBias[2 * 32 + o];
        v.w = rf[((3 * 128 + b) * 34) + o] + sBias[3 * 32 + o];
        *reinterpret_cast<float4*>(&out[((size_t)(b * 32 + o)) * 3600 + pos0]) = v;
    }
}

// ---------------------------------------------------------------- launch
extern "C" void kernel_launch(void* const* d_in, const int* in_sizes, int n_in,
                              void* d_out, int out_size)
{
    const float* x    = (const float*)d_in[0];
    const float* W    = (const float*)d_in[1];
    const float* bias = (const float*)d_in[2];
    float* out        = (float*)d_out;

    cudaFuncSetAttribute(lc2d_hmma_kernel,
                         cudaFuncAttributeMaxDynamicSharedMemorySize, SMEM_TOTAL);

    prep_x_kernel<<<dim3(8, 64, 3), dim3(32, 8)>>>(x);
    lc2d_hmma_kernel<<<dim3(RYX / TX, RYX), 256, SMEM_TOTAL>>>(W, bias, out);
}